// round 12
// baseline (speedup 1.0000x reference)
#include <cuda_runtime.h>

#define B_    4
#define Qn    256
#define Kn    1024
#define Din   256
#define H_    128
#define Vn    256
#define NSEG  4
#define AVCH  4      // BK-phases (64k each) per AV work item

// Scratch (no cudaMalloc allowed)
__device__ float d_qproj[B_ * Qn * H_];          // [b*Q+q][h]
__device__ float d_kproj[B_ * Kn * H_];          // [b*K+k][h]
__device__ float d_scores[B_ * Qn * Kn];         // p = exp(score - B), zero beyond valid
__device__ float d_accp[NSEG][B_ * Qn * Vn];     // chunked partial AV
__device__ float d_sump[NSEG][B_ * Qn];          // chunked partial row sums

__device__ __forceinline__ float tanh_fast(float x) {
    float y;
    asm("tanh.approx.f32 %0, %1;" : "=f"(y) : "f"(x));
    return y;
}

// ---------------------------------------------------------------------------
// Kernel 1: projection GEMM with INLINE W transpose.
// out[row][h] = dot(X[row,:], W[h,:])   (torch Linear)
// BM=16, BN=128(H), BK=32.  256 threads, 2x4 microtile.  grid=320.
// W tile staged transposed: Bs[kk][h] <- W[h][k0+kk] via scalar STS
// (bank-conflict-free: (4*kk + h) spans all 32 banks per STS).
// ---------------------------------------------------------------------------
__global__ __launch_bounds__(256) void proj_gemm(const float* __restrict__ Xq,
                                                 const float* __restrict__ Xk,
                                                 const float* __restrict__ Wq,
                                                 const float* __restrict__ Wk) {
    const int blk = blockIdx.x;
    const float* X; const float* W; float* out; int row0;
    if (blk < 64) { X = Xq; W = Wq; out = d_qproj; row0 = blk * 16; }
    else          { X = Xk; W = Wk; out = d_kproj; row0 = (blk - 64) * 16; }

    __shared__ float As[32][17];
    __shared__ float Bs[32][132];    // [kk][h], padded: row stride 132 (16B-aligned)

    const int tid = threadIdx.x;
    const int tx = tid & 31, ty = tid >> 5;
    float acc[2][4] = {};

    for (int k0 = 0; k0 < Din; k0 += 32) {
        if (tid < 128) {
            const int r = tid >> 3, f = tid & 7;
            float4 v = *(const float4*)&X[(row0 + r) * Din + k0 + f * 4];
            As[f * 4 + 0][r] = v.x; As[f * 4 + 1][r] = v.y;
            As[f * 4 + 2][r] = v.z; As[f * 4 + 3][r] = v.w;
        }
        // W tile: idx = tid*4+i over 0..1023; h = idx>>3, f = idx&7
        #pragma unroll
        for (int i = 0; i < 4; i++) {
            const int idx = tid * 4 + i;
            const int h = idx >> 3, f = idx & 7;
            float4 v = *(const float4*)&W[h * Din + k0 + f * 4];
            Bs[f * 4 + 0][h] = v.x; Bs[f * 4 + 1][h] = v.y;
            Bs[f * 4 + 2][h] = v.z; Bs[f * 4 + 3][h] = v.w;
        }
        __syncthreads();

        #pragma unroll
        for (int kk = 0; kk < 32; kk++) {
            const float a0 = As[kk][ty * 2 + 0];
            const float a1 = As[kk][ty * 2 + 1];
            const float4 bv = *(const float4*)&Bs[kk][tx * 4];
            acc[0][0] = fmaf(a0, bv.x, acc[0][0]); acc[0][1] = fmaf(a0, bv.y, acc[0][1]);
            acc[0][2] = fmaf(a0, bv.z, acc[0][2]); acc[0][3] = fmaf(a0, bv.w, acc[0][3]);
            acc[1][0] = fmaf(a1, bv.x, acc[1][0]); acc[1][1] = fmaf(a1, bv.y, acc[1][1]);
            acc[1][2] = fmaf(a1, bv.z, acc[1][2]); acc[1][3] = fmaf(a1, bv.w, acc[1][3]);
        }
        __syncthreads();
    }
    #pragma unroll
    for (int m = 0; m < 2; m++) {
        float4 v = make_float4(acc[m][0], acc[m][1], acc[m][2], acc[m][3]);
        *(float4*)&out[(row0 + ty * 2 + m) * H_ + tx * 4] = v;
    }
}

// ---------------------------------------------------------------------------
// Kernel 2: scores, static strided schedule over live tiles.  grid = 444.
// Computes B = sum|wv| locally (uniform, bitwise-deterministic).
// ---------------------------------------------------------------------------
__global__ __launch_bounds__(256) void score_kernel(const int* __restrict__ valid_lens,
                                                    const float* __restrict__ wv) {
    __shared__ float kt_s[64][132];
    __shared__ float qs[32 * 128];
    __shared__ float wvs[128];
    __shared__ float Bsh_s;

    const int tid = threadIdx.x, lane = tid & 31, w = tid >> 5;

    int vl[4], nkt[4];
    int tot = 0;
    #pragma unroll
    for (int bb = 0; bb < 4; bb++) {
        vl[bb] = valid_lens[bb];
        nkt[bb] = (vl[bb] + 63) >> 6;
        tot += nkt[bb] * 8;
    }
    if (tid < 128) wvs[tid] = wv[tid];
    if (w == 0) {                     // B = sum |wv| (same order as before)
        float s = 0.f;
        #pragma unroll
        for (int i = 0; i < 4; i++) s += fabsf(wv[lane + 32 * i]);
        #pragma unroll
        for (int off = 16; off; off >>= 1)
            s += __shfl_xor_sync(0xffffffffu, s, off);
        if (lane == 0) Bsh_s = s;
    }
    __syncthreads();
    const float Bsh = Bsh_s;

    for (int wk = blockIdx.x; wk < tot; wk += gridDim.x) {
        int rem = wk, b = 0;
        while (b < 3 && rem >= nkt[b] * 8) { rem -= nkt[b] * 8; b++; }
        const int ktl = rem >> 3, qt = rem & 7;
        const int q0 = qt * 32, k0 = ktl * 64;
        const int valid = vl[b];

        {
            const float4* __restrict__ src = (const float4*)(d_qproj + (b * Qn + q0) * H_);
            #pragma unroll
            for (int i = 0; i < 4; i++)
                ((float4*)qs)[tid + 256 * i] = src[tid + 256 * i];
        }
        #pragma unroll
        for (int i = 0; i < 8; i++) {
            const int idx = tid + 256 * i;
            const int kl = idx >> 5, f = idx & 31;
            *(float4*)&kt_s[kl][f * 4] =
                *(const float4*)&d_kproj[(b * Kn + k0 + kl) * H_ + f * 4];
        }
        __syncthreads();

        const int klh = (w & 1) * 32 + lane;
        const int qb  = (w >> 1) * 8;
        const int kg  = k0 + klh;

        float acc[8] = {};
        #pragma unroll
        for (int h0 = 0; h0 < 128; h0 += 16) {
            const float4 kv0 = *(const float4*)&kt_s[klh][h0 + 0];
            const float4 kv1 = *(const float4*)&kt_s[klh][h0 + 4];
            const float4 kv2 = *(const float4*)&kt_s[klh][h0 + 8];
            const float4 kv3 = *(const float4*)&kt_s[klh][h0 + 12];
            const float4 w0 = *(const float4*)&wvs[h0 + 0];
            const float4 w1 = *(const float4*)&wvs[h0 + 4];
            const float4 w2 = *(const float4*)&wvs[h0 + 8];
            const float4 w3 = *(const float4*)&wvs[h0 + 12];
            #pragma unroll
            for (int qi = 0; qi < 8; qi++) {
                const float* __restrict__ qrow = qs + (qb + qi) * 128 + h0;
                const float4 q0v = *(const float4*)&qrow[0];
                const float4 q1v = *(const float4*)&qrow[4];
                const float4 q2v = *(const float4*)&qrow[8];
                const float4 q3v = *(const float4*)&qrow[12];
                float a = acc[qi];
                a = fmaf(w0.x, tanh_fast(q0v.x + kv0.x), a);
                a = fmaf(w0.y, tanh_fast(q0v.y + kv0.y), a);
                a = fmaf(w0.z, tanh_fast(q0v.z + kv0.z), a);
                a = fmaf(w0.w, tanh_fast(q0v.w + kv0.w), a);
                a = fmaf(w1.x, tanh_fast(q1v.x + kv1.x), a);
                a = fmaf(w1.y, tanh_fast(q1v.y + kv1.y), a);
                a = fmaf(w1.z, tanh_fast(q1v.z + kv1.z), a);
                a = fmaf(w1.w, tanh_fast(q1v.w + kv1.w), a);
                a = fmaf(w2.x, tanh_fast(q2v.x + kv2.x), a);
                a = fmaf(w2.y, tanh_fast(q2v.y + kv2.y), a);
                a = fmaf(w2.z, tanh_fast(q2v.z + kv2.z), a);
                a = fmaf(w2.w, tanh_fast(q2v.w + kv2.w), a);
                a = fmaf(w3.x, tanh_fast(q3v.x + kv3.x), a);
                a = fmaf(w3.y, tanh_fast(q3v.y + kv3.y), a);
                a = fmaf(w3.z, tanh_fast(q3v.z + kv3.z), a);
                a = fmaf(w3.w, tanh_fast(q3v.w + kv3.w), a);
                acc[qi] = a;
            }
        }

        const bool live = (kg < valid);
        #pragma unroll
        for (int qi = 0; qi < 8; qi++) {
            const float p = live ? __expf(acc[qi] - Bsh) : 0.f;
            d_scores[(b * Qn + q0 + qb + qi) * Kn + kg] = p;
        }
        __syncthreads();
    }
}

// ---------------------------------------------------------------------------
// Kernel 3: AV partials, static strided schedule.  grid = 740, 128 threads.
// Work item = (b, chunk c, qt, vt): BK-phases [4c, min(4c+4, nPh_b)).
// Tile 16q x 64v, 2q x 4v microtile, double-buffered smem.
// ---------------------------------------------------------------------------
__global__ __launch_bounds__(128) void av_gemm_s(const float* __restrict__ values,
                                                 const int* __restrict__ valid_lens) {
    __shared__ float As[2][16][68];
    __shared__ float Bs[2][64][68];

    const int tid = threadIdx.x;
    const int tx = tid & 15, ty = tid >> 4;

    int nPh[4], cb[4];
    int tot = 0;
    #pragma unroll
    for (int bb = 0; bb < 4; bb++) {
        nPh[bb] = ((valid_lens[bb] + 63) & ~63) >> 6;
        cb[bb]  = (nPh[bb] + AVCH - 1) / AVCH;
        tot += 64 * cb[bb];
    }

    for (int wk = blockIdx.x; wk < tot; wk += gridDim.x) {
        int rem = wk, b = 0;
        while (b < 3 && rem >= 64 * cb[b]) { rem -= 64 * cb[b]; b++; }
        const int c  = rem >> 6;
        const int sp = rem & 63;
        const int qt = sp >> 2, vt = sp & 3;
        const int q0 = qt * 16, v0 = vt * 64;
        const int phA = AVCH * c;
        const int phB = min(nPh[b], AVCH * c + AVCH);

        const float* __restrict__ a0p = d_scores + (b * Qn + q0 + ty)     * Kn + tx * 4;
        const float* __restrict__ a1p = d_scores + (b * Qn + q0 + ty + 8) * Kn + tx * 4;
        const float* __restrict__ vbase = values + ((size_t)b * Kn + ty) * Vn + v0 + tx * 4;

        float4 acc0 = make_float4(0.f, 0.f, 0.f, 0.f);
        float4 acc1 = make_float4(0.f, 0.f, 0.f, 0.f);
        float sum0 = 0.f, sum1 = 0.f;

        float4 pa[2], pb[8];
        {
            const int k00 = phA * 64;
            pa[0] = *(const float4*)&a0p[k00];
            pa[1] = *(const float4*)&a1p[k00];
            #pragma unroll
            for (int i = 0; i < 8; i++)
                pb[i] = *(const float4*)&vbase[(size_t)(k00 + 8 * i) * Vn];
        }
        *(float4*)&As[0][ty][tx * 4]     = pa[0];
        *(float4*)&As[0][ty + 8][tx * 4] = pa[1];
        #pragma unroll
        for (int i = 0; i < 8; i++)
            *(float4*)&Bs[0][ty + 8 * i][tx * 4] = pb[i];
        __syncthreads();

        for (int ph = phA; ph < phB; ph++) {
            const int buf = (ph - phA) & 1;
            if (ph + 1 < phB) {
                const int k0n = (ph + 1) * 64;
                pa[0] = *(const float4*)&a0p[k0n];
                pa[1] = *(const float4*)&a1p[k0n];
                #pragma unroll
                for (int i = 0; i < 8; i++)
                    pb[i] = *(const float4*)&vbase[(size_t)(k0n + 8 * i) * Vn];
            }

            #pragma unroll
            for (int kk4 = 0; kk4 < 16; kk4++) {
                const float4 a0 = *(const float4*)&As[buf][2 * ty + 0][kk4 * 4];
                const float4 a1 = *(const float4*)&As[buf][2 * ty + 1][kk4 * 4];
                sum0 += (a0.x + a0.y) + (a0.z + a0.w);
                sum1 += (a1.x + a1.y) + (a1.z + a1.w);
                {
                    const float4 bv = *(const float4*)&Bs[buf][kk4 * 4 + 0][tx * 4];
                    acc0.x = fmaf(a0.x, bv.x, acc0.x); acc0.y = fmaf(a0.x, bv.y, acc0.y);
                    acc0.z = fmaf(a0.x, bv.z, acc0.z); acc0.w = fmaf(a0.x, bv.w, acc0.w);
                    acc1.x = fmaf(a1.x, bv.x, acc1.x); acc1.y = fmaf(a1.x, bv.y, acc1.y);
                    acc1.z = fmaf(a1.x, bv.z, acc1.z); acc1.w = fmaf(a1.x, bv.w, acc1.w);
                }
                {
                    const float4 bv = *(const float4*)&Bs[buf][kk4 * 4 + 1][tx * 4];
                    acc0.x = fmaf(a0.y, bv.x, acc0.x); acc0.y = fmaf(a0.y, bv.y, acc0.y);
                    acc0.z = fmaf(a0.y, bv.z, acc0.z); acc0.w = fmaf(a0.y, bv.w, acc0.w);
                    acc1.x = fmaf(a1.y, bv.x, acc1.x); acc1.y = fmaf(a1.y, bv.y, acc1.y);
                    acc1.z = fmaf(a1.y, bv.z, acc1.z); acc1.w = fmaf(a1.y, bv.w, acc1.w);
                }
                {
                    const float4 bv = *(const float4*)&Bs[buf][kk4 * 4 + 2][tx * 4];
                    acc0.x = fmaf(a0.z, bv.x, acc0.x); acc0.y = fmaf(a0.z, bv.y, acc0.y);
                    acc0.z = fmaf(a0.z, bv.z, acc0.z); acc0.w = fmaf(a0.z, bv.w, acc0.w);
                    acc1.x = fmaf(a1.z, bv.x, acc1.x); acc1.y = fmaf(a1.z, bv.y, acc1.y);
                    acc1.z = fmaf(a1.z, bv.z, acc1.z); acc1.w = fmaf(a1.z, bv.w, acc1.w);
                }
                {
                    const float4 bv = *(const float4*)&Bs[buf][kk4 * 4 + 3][tx * 4];
                    acc0.x = fmaf(a0.w, bv.x, acc0.x); acc0.y = fmaf(a0.w, bv.y, acc0.y);
                    acc0.z = fmaf(a0.w, bv.z, acc0.z); acc0.w = fmaf(a0.w, bv.w, acc0.w);
                    acc1.x = fmaf(a1.w, bv.x, acc1.x); acc1.y = fmaf(a1.w, bv.y, acc1.y);
                    acc1.z = fmaf(a1.w, bv.z, acc1.z); acc1.w = fmaf(a1.w, bv.w, acc1.w);
                }
            }

            if (ph + 1 < phB) {
                const int nb = buf ^ 1;
                *(float4*)&As[nb][ty][tx * 4]     = pa[0];
                *(float4*)&As[nb][ty + 8][tx * 4] = pa[1];
                #pragma unroll
                for (int i = 0; i < 8; i++)
                    *(float4*)&Bs[nb][ty + 8 * i][tx * 4] = pb[i];
            }
            __syncthreads();
        }

        float* ap = &d_accp[c][(b * Qn + q0 + 2 * ty) * Vn + v0 + tx * 4];
        *(float4*)ap = acc0;
        *(float4*)(ap + Vn) = acc1;
        if (vt == 0 && tx == 0) {
            d_sump[c][b * Qn + q0 + 2 * ty + 0] = sum0;
            d_sump[c][b * Qn + q0 + 2 * ty + 1] = sum1;
        }
    }
}

// ---------------------------------------------------------------------------
// Kernel 4: combine live chunks + normalize.  grid 256 x 256, float4/thread.
// ---------------------------------------------------------------------------
__global__ __launch_bounds__(256) void combine(const int* __restrict__ valid_lens,
                                               float* __restrict__ out) {
    const int i4 = blockIdx.x * 256 + threadIdx.x;
    const int q  = i4 >> 6;
    const int b  = q >> 8;
    const int nPh = ((valid_lens[b] + 63) & ~63) >> 6;
    const int cbn = (nPh + AVCH - 1) / AVCH;

    float4 a = make_float4(0.f, 0.f, 0.f, 0.f);
    float ssum = 0.f;
    for (int s = 0; s < cbn; s++) {
        const float4 p = ((const float4*)d_accp[s])[i4];
        a.x += p.x; a.y += p.y; a.z += p.z; a.w += p.w;
        ssum += d_sump[s][q];
    }
    const float inv = 1.0f / ssum;
    a.x *= inv; a.y *= inv; a.z *= inv; a.w *= inv;
    ((float4*)out)[i4] = a;
}

extern "C" void kernel_launch(void* const* d_in, const int* in_sizes, int n_in,
                              void* d_out, int out_size) {
    const float* queries    = (const float*)d_in[0];
    const float* keys       = (const float*)d_in[1];
    const float* values     = (const float*)d_in[2];
    const int*   valid_lens = (const int*)  d_in[3];
    const float* W_q        = (const float*)d_in[4];
    const float* W_k        = (const float*)d_in[5];
    const float* w_v        = (const float*)d_in[6];
    float* out              = (float*)d_out;

    proj_gemm<<<320, 256>>>(queries, keys, W_q, W_k);
    score_kernel<<<444, 256>>>(valid_lens, w_v);
    av_gemm_s<<<740, 128>>>(values, valid_lens);
    combine<<<256, 256>>>(valid_lens, out);
}

// round 13
// speedup vs baseline: 1.0854x; 1.0854x over previous
#include <cuda_runtime.h>

#define B_    4
#define Qn    256
#define Kn    1024
#define Din   256
#define H_    128
#define Vn    256
#define NSEG  8

// Scratch (no cudaMalloc allowed)
__device__ float d_qproj[B_ * Qn * H_];          // [b*Q+q][h]
__device__ float d_kproj[B_ * Kn * H_];          // [b*K+k][h]
__device__ float d_scores[B_ * Qn * Kn];         // p = exp(score - B), zero beyond valid
__device__ float d_WqT[Din * H_];                // [i][h]
__device__ float d_WkT[Din * H_];                // [i][h]
__device__ float d_B;                            // exp shift = sum |w_v|
__device__ float d_accp[NSEG][B_ * Qn * Vn];     // chunked partial AV
__device__ float d_sump[NSEG][B_ * Qn];          // chunked partial row sums

__device__ __forceinline__ float tanh_fast(float x) {
    float y;
    asm("tanh.approx.f32 %0, %1;" : "=f"(y) : "f"(x));
    return y;
}

// ---------------------------------------------------------------------------
// Kernel 0: transpose W [H,Din] -> WT [Din,H]  (blocks 0..63)
//           block 64: d_B = sum |w_v|
// ---------------------------------------------------------------------------
__global__ __launch_bounds__(256) void transpose_w(const float* __restrict__ Wq,
                                                   const float* __restrict__ Wk,
                                                   const float* __restrict__ wv) {
    const int blk = blockIdx.x;
    if (blk == 64) {
        if (threadIdx.x < 32) {
            float s = 0.f;
            #pragma unroll
            for (int i = 0; i < 4; i++) s += fabsf(wv[threadIdx.x + 32 * i]);
            #pragma unroll
            for (int off = 16; off; off >>= 1)
                s += __shfl_xor_sync(0xffffffffu, s, off);
            if (threadIdx.x == 0) d_B = s;
        }
        return;
    }
    const int mat = blk >> 5;
    const int t   = blk & 31;
    const int i0 = (t >> 2) * 32;
    const int h0 = (t & 3) * 32;
    const float* __restrict__ W = mat ? Wk : Wq;
    float* __restrict__ WT      = mat ? d_WkT : d_WqT;

    __shared__ float ts[32][33];
    const int tx = threadIdx.x & 31, ty = threadIdx.x >> 5;
    #pragma unroll
    for (int r = 0; r < 4; r++)
        ts[ty + 8 * r][tx] = W[(h0 + ty + 8 * r) * Din + i0 + tx];
    __syncthreads();
    #pragma unroll
    for (int r = 0; r < 4; r++)
        WT[(i0 + ty + 8 * r) * H_ + h0 + tx] = ts[tx][ty + 8 * r];
}

// ---------------------------------------------------------------------------
// Kernel 1: projection GEMM.  BM=16, BN=128, BK=32.  grid=320.
// ---------------------------------------------------------------------------
__global__ __launch_bounds__(256) void proj_gemm(const float* __restrict__ Xq,
                                                 const float* __restrict__ Xk) {
    const int blk = blockIdx.x;
    const float* X; const float* WT; float* out; int row0;
    if (blk < 64) { X = Xq; WT = d_WqT; out = d_qproj; row0 = blk * 16; }
    else          { X = Xk; WT = d_WkT; out = d_kproj; row0 = (blk - 64) * 16; }

    __shared__ float As[32][17];
    __shared__ float Bs[32][128];

    const int tid = threadIdx.x;
    const int tx = tid & 31, ty = tid >> 5;
    float acc[2][4] = {};

    for (int k0 = 0; k0 < Din; k0 += 32) {
        if (tid < 128) {
            const int r = tid >> 3, f = tid & 7;
            float4 v = *(const float4*)&X[(row0 + r) * Din + k0 + f * 4];
            As[f * 4 + 0][r] = v.x; As[f * 4 + 1][r] = v.y;
            As[f * 4 + 2][r] = v.z; As[f * 4 + 3][r] = v.w;
        }
        #pragma unroll
        for (int i = 0; i < 4; i++) {
            const int idx = tid + 256 * i;
            const int kk = idx >> 5, f = idx & 31;
            *(float4*)&Bs[kk][f * 4] = *(const float4*)&WT[(k0 + kk) * H_ + f * 4];
        }
        __syncthreads();

        #pragma unroll
        for (int kk = 0; kk < 32; kk++) {
            const float a0 = As[kk][ty * 2 + 0];
            const float a1 = As[kk][ty * 2 + 1];
            const float4 bv = *(const float4*)&Bs[kk][tx * 4];
            acc[0][0] = fmaf(a0, bv.x, acc[0][0]); acc[0][1] = fmaf(a0, bv.y, acc[0][1]);
            acc[0][2] = fmaf(a0, bv.z, acc[0][2]); acc[0][3] = fmaf(a0, bv.w, acc[0][3]);
            acc[1][0] = fmaf(a1, bv.x, acc[1][0]); acc[1][1] = fmaf(a1, bv.y, acc[1][1]);
            acc[1][2] = fmaf(a1, bv.z, acc[1][2]); acc[1][3] = fmaf(a1, bv.w, acc[1][3]);
        }
        __syncthreads();
    }
    #pragma unroll
    for (int m = 0; m < 2; m++) {
        float4 v = make_float4(acc[m][0], acc[m][1], acc[m][2], acc[m][3]);
        *(float4*)&out[(row0 + ty * 2 + m) * H_ + tx * 4] = v;
    }
}

// ---------------------------------------------------------------------------
// Kernel 2: scores, static strided schedule over live tiles.  grid = 444.
// ---------------------------------------------------------------------------
__global__ __launch_bounds__(256) void score_kernel(const int* __restrict__ valid_lens,
                                                    const float* __restrict__ wv) {
    __shared__ float kt_s[64][132];
    __shared__ float qs[32 * 128];
    __shared__ float wvs[128];

    const int tid = threadIdx.x, lane = tid & 31, w = tid >> 5;

    int vl[4], nkt[4];
    int tot = 0;
    #pragma unroll
    for (int bb = 0; bb < 4; bb++) {
        vl[bb] = valid_lens[bb];
        nkt[bb] = (vl[bb] + 63) >> 6;
        tot += nkt[bb] * 8;
    }
    const float Bsh = d_B;
    if (tid < 128) wvs[tid] = wv[tid];
    __syncthreads();

    for (int wk = blockIdx.x; wk < tot; wk += gridDim.x) {
        int rem = wk, b = 0;
        while (b < 3 && rem >= nkt[b] * 8) { rem -= nkt[b] * 8; b++; }
        const int ktl = rem >> 3, qt = rem & 7;
        const int q0 = qt * 32, k0 = ktl * 64;
        const int valid = vl[b];

        {
            const float4* __restrict__ src = (const float4*)(d_qproj + (b * Qn + q0) * H_);
            #pragma unroll
            for (int i = 0; i < 4; i++)
                ((float4*)qs)[tid + 256 * i] = src[tid + 256 * i];
        }
        #pragma unroll
        for (int i = 0; i < 8; i++) {
            const int idx = tid + 256 * i;
            const int kl = idx >> 5, f = idx & 31;
            *(float4*)&kt_s[kl][f * 4] =
                *(const float4*)&d_kproj[(b * Kn + k0 + kl) * H_ + f * 4];
        }
        __syncthreads();

        const int klh = (w & 1) * 32 + lane;
        const int qb  = (w >> 1) * 8;
        const int kg  = k0 + klh;

        float acc[8] = {};
        #pragma unroll
        for (int h0 = 0; h0 < 128; h0 += 16) {
            const float4 kv0 = *(const float4*)&kt_s[klh][h0 + 0];
            const float4 kv1 = *(const float4*)&kt_s[klh][h0 + 4];
            const float4 kv2 = *(const float4*)&kt_s[klh][h0 + 8];
            const float4 kv3 = *(const float4*)&kt_s[klh][h0 + 12];
            const float4 w0 = *(const float4*)&wvs[h0 + 0];
            const float4 w1 = *(const float4*)&wvs[h0 + 4];
            const float4 w2 = *(const float4*)&wvs[h0 + 8];
            const float4 w3 = *(const float4*)&wvs[h0 + 12];
            #pragma unroll
            for (int qi = 0; qi < 8; qi++) {
                const float* __restrict__ qrow = qs + (qb + qi) * 128 + h0;
                const float4 q0v = *(const float4*)&qrow[0];
                const float4 q1v = *(const float4*)&qrow[4];
                const float4 q2v = *(const float4*)&qrow[8];
                const float4 q3v = *(const float4*)&qrow[12];
                float a = acc[qi];
                a = fmaf(w0.x, tanh_fast(q0v.x + kv0.x), a);
                a = fmaf(w0.y, tanh_fast(q0v.y + kv0.y), a);
                a = fmaf(w0.z, tanh_fast(q0v.z + kv0.z), a);
                a = fmaf(w0.w, tanh_fast(q0v.w + kv0.w), a);
                a = fmaf(w1.x, tanh_fast(q1v.x + kv1.x), a);
                a = fmaf(w1.y, tanh_fast(q1v.y + kv1.y), a);
                a = fmaf(w1.z, tanh_fast(q1v.z + kv1.z), a);
                a = fmaf(w1.w, tanh_fast(q1v.w + kv1.w), a);
                a = fmaf(w2.x, tanh_fast(q2v.x + kv2.x), a);
                a = fmaf(w2.y, tanh_fast(q2v.y + kv2.y), a);
                a = fmaf(w2.z, tanh_fast(q2v.z + kv2.z), a);
                a = fmaf(w2.w, tanh_fast(q2v.w + kv2.w), a);
                a = fmaf(w3.x, tanh_fast(q3v.x + kv3.x), a);
                a = fmaf(w3.y, tanh_fast(q3v.y + kv3.y), a);
                a = fmaf(w3.z, tanh_fast(q3v.z + kv3.z), a);
                a = fmaf(w3.w, tanh_fast(q3v.w + kv3.w), a);
                acc[qi] = a;
            }
        }

        const bool live = (kg < valid);
        #pragma unroll
        for (int qi = 0; qi < 8; qi++) {
            const float p = live ? __expf(acc[qi] - Bsh) : 0.f;
            d_scores[(b * Qn + q0 + qb + qi) * Kn + kg] = p;
        }
        __syncthreads();
    }
}

// ---------------------------------------------------------------------------
// Kernel 3: AV partials, static strided schedule.  grid = 1480, 128 threads.
// Work item = (b, chunk c, qt, vt): BK-phases [2c, min(2c+2, nPh_b)).
// SINGLE-buffered smem (21.8KB -> 10 blocks/SM resident); next phase is
// prefetched into registers, committed after a sync.
// ---------------------------------------------------------------------------
__global__ __launch_bounds__(128) void av_gemm_s(const float* __restrict__ values,
                                                 const int* __restrict__ valid_lens) {
    __shared__ float As[16][68];
    __shared__ float Bs[64][68];

    const int tid = threadIdx.x;
    const int tx = tid & 15, ty = tid >> 4;

    int nPh[4], cb[4];
    int tot = 0;
    #pragma unroll
    for (int bb = 0; bb < 4; bb++) {
        nPh[bb] = ((valid_lens[bb] + 63) & ~63) >> 6;
        cb[bb]  = (nPh[bb] + 1) >> 1;
        tot += 64 * cb[bb];
    }

    for (int wk = blockIdx.x; wk < tot; wk += gridDim.x) {
        int rem = wk, b = 0;
        while (b < 3 && rem >= 64 * cb[b]) { rem -= 64 * cb[b]; b++; }
        const int c  = rem >> 6;
        const int sp = rem & 63;
        const int qt = sp >> 2, vt = sp & 3;
        const int q0 = qt * 16, v0 = vt * 64;
        const int phA = 2 * c;
        const int phB = min(nPh[b], 2 * c + 2);

        const float* __restrict__ a0p = d_scores + (b * Qn + q0 + ty)     * Kn + tx * 4;
        const float* __restrict__ a1p = d_scores + (b * Qn + q0 + ty + 8) * Kn + tx * 4;
        const float* __restrict__ vbase = values + ((size_t)b * Kn + ty) * Vn + v0 + tx * 4;

        float4 acc0 = make_float4(0.f, 0.f, 0.f, 0.f);
        float4 acc1 = make_float4(0.f, 0.f, 0.f, 0.f);
        float sum0 = 0.f, sum1 = 0.f;

        float4 pa[2], pb[8];
        {
            const int k00 = phA * 64;
            pa[0] = *(const float4*)&a0p[k00];
            pa[1] = *(const float4*)&a1p[k00];
            #pragma unroll
            for (int i = 0; i < 8; i++)
                pb[i] = *(const float4*)&vbase[(size_t)(k00 + 8 * i) * Vn];
        }
        *(float4*)&As[ty][tx * 4]     = pa[0];
        *(float4*)&As[ty + 8][tx * 4] = pa[1];
        #pragma unroll
        for (int i = 0; i < 8; i++)
            *(float4*)&Bs[ty + 8 * i][tx * 4] = pb[i];
        __syncthreads();

        for (int ph = phA; ph < phB; ph++) {
            if (ph + 1 < phB) {   // prefetch next phase into registers
                const int k0n = (ph + 1) * 64;
                pa[0] = *(const float4*)&a0p[k0n];
                pa[1] = *(const float4*)&a1p[k0n];
                #pragma unroll
                for (int i = 0; i < 8; i++)
                    pb[i] = *(const float4*)&vbase[(size_t)(k0n + 8 * i) * Vn];
            }

            #pragma unroll
            for (int kk4 = 0; kk4 < 16; kk4++) {
                const float4 a0 = *(const float4*)&As[2 * ty + 0][kk4 * 4];
                const float4 a1 = *(const float4*)&As[2 * ty + 1][kk4 * 4];
                sum0 += (a0.x + a0.y) + (a0.z + a0.w);
                sum1 += (a1.x + a1.y) + (a1.z + a1.w);
                {
                    const float4 bv = *(const float4*)&Bs[kk4 * 4 + 0][tx * 4];
                    acc0.x = fmaf(a0.x, bv.x, acc0.x); acc0.y = fmaf(a0.x, bv.y, acc0.y);
                    acc0.z = fmaf(a0.x, bv.z, acc0.z); acc0.w = fmaf(a0.x, bv.w, acc0.w);
                    acc1.x = fmaf(a1.x, bv.x, acc1.x); acc1.y = fmaf(a1.x, bv.y, acc1.y);
                    acc1.z = fmaf(a1.x, bv.z, acc1.z); acc1.w = fmaf(a1.x, bv.w, acc1.w);
                }
                {
                    const float4 bv = *(const float4*)&Bs[kk4 * 4 + 1][tx * 4];
                    acc0.x = fmaf(a0.y, bv.x, acc0.x); acc0.y = fmaf(a0.y, bv.y, acc0.y);
                    acc0.z = fmaf(a0.y, bv.z, acc0.z); acc0.w = fmaf(a0.y, bv.w, acc0.w);
                    acc1.x = fmaf(a1.y, bv.x, acc1.x); acc1.y = fmaf(a1.y, bv.y, acc1.y);
                    acc1.z = fmaf(a1.y, bv.z, acc1.z); acc1.w = fmaf(a1.y, bv.w, acc1.w);
                }
                {
                    const float4 bv = *(const float4*)&Bs[kk4 * 4 + 2][tx * 4];
                    acc0.x = fmaf(a0.z, bv.x, acc0.x); acc0.y = fmaf(a0.z, bv.y, acc0.y);
                    acc0.z = fmaf(a0.z, bv.z, acc0.z); acc0.w = fmaf(a0.z, bv.w, acc0.w);
                    acc1.x = fmaf(a1.z, bv.x, acc1.x); acc1.y = fmaf(a1.z, bv.y, acc1.y);
                    acc1.z = fmaf(a1.z, bv.z, acc1.z); acc1.w = fmaf(a1.z, bv.w, acc1.w);
                }
                {
                    const float4 bv = *(const float4*)&Bs[kk4 * 4 + 3][tx * 4];
                    acc0.x = fmaf(a0.w, bv.x, acc0.x); acc0.y = fmaf(a0.w, bv.y, acc0.y);
                    acc0.z = fmaf(a0.w, bv.z, acc0.z); acc0.w = fmaf(a0.w, bv.w, acc0.w);
                    acc1.x = fmaf(a1.w, bv.x, acc1.x); acc1.y = fmaf(a1.w, bv.y, acc1.y);
                    acc1.z = fmaf(a1.w, bv.z, acc1.z); acc1.w = fmaf(a1.w, bv.w, acc1.w);
                }
            }
            __syncthreads();               // all reads of this phase done

            if (ph + 1 < phB) {            // commit prefetched regs to smem
                *(float4*)&As[ty][tx * 4]     = pa[0];
                *(float4*)&As[ty + 8][tx * 4] = pa[1];
                #pragma unroll
                for (int i = 0; i < 8; i++)
                    *(float4*)&Bs[ty + 8 * i][tx * 4] = pb[i];
                __syncthreads();
            }
        }

        float* ap = &d_accp[c][(b * Qn + q0 + 2 * ty) * Vn + v0 + tx * 4];
        *(float4*)ap = acc0;
        *(float4*)(ap + Vn) = acc1;
        if (vt == 0 && tx == 0) {
            d_sump[c][b * Qn + q0 + 2 * ty + 0] = sum0;
            d_sump[c][b * Qn + q0 + 2 * ty + 1] = sum1;
        }
    }
}

// ---------------------------------------------------------------------------
// Kernel 4: combine live chunks + normalize.  grid 256 x 256, float4/thread.
// ---------------------------------------------------------------------------
__global__ __launch_bounds__(256) void combine(const int* __restrict__ valid_lens,
                                               float* __restrict__ out) {
    const int i4 = blockIdx.x * 256 + threadIdx.x;
    const int q  = i4 >> 6;
    const int b  = q >> 8;
    const int nPh = ((valid_lens[b] + 63) & ~63) >> 6;
    const int cbn = (nPh + 1) >> 1;

    float4 a = make_float4(0.f, 0.f, 0.f, 0.f);
    float ssum = 0.f;
    for (int s = 0; s < cbn; s++) {
        const float4 p = ((const float4*)d_accp[s])[i4];
        a.x += p.x; a.y += p.y; a.z += p.z; a.w += p.w;
        ssum += d_sump[s][q];
    }
    const float inv = 1.0f / ssum;
    a.x *= inv; a.y *= inv; a.z *= inv; a.w *= inv;
    ((float4*)out)[i4] = a;
}

extern "C" void kernel_launch(void* const* d_in, const int* in_sizes, int n_in,
                              void* d_out, int out_size) {
    const float* queries    = (const float*)d_in[0];
    const float* keys       = (const float*)d_in[1];
    const float* values     = (const float*)d_in[2];
    const int*   valid_lens = (const int*)  d_in[3];
    const float* W_q        = (const float*)d_in[4];
    const float* W_k        = (const float*)d_in[5];
    const float* w_v        = (const float*)d_in[6];
    float* out              = (float*)d_out;

    transpose_w<<<65, 256>>>(W_q, W_k, w_v);
    proj_gemm<<<320, 256>>>(queries, keys);
    score_kernel<<<444, 256>>>(valid_lens, w_v);
    av_gemm_s<<<1480, 128>>>(values, valid_lens);
    combine<<<256, 256>>>(valid_lens, out);
}

// round 14
// speedup vs baseline: 1.1113x; 1.0239x over previous
#include <cuda_runtime.h>

#define B_    4
#define Qn    256
#define Kn    1024
#define Din   256
#define H_    128
#define Vn    256
#define NSEG  8

// Scratch (no cudaMalloc allowed)
__device__ float d_qproj[B_ * Qn * H_];          // [b*Q+q][h]
__device__ float d_kproj[B_ * Kn * H_];          // [b*K+k][h]
__device__ float d_scores[B_ * Qn * Kn];         // p = exp(score - B), zero beyond valid
__device__ float d_WqT[Din * H_];                // [i][h]
__device__ float d_WkT[Din * H_];                // [i][h]
__device__ float d_B;                            // exp shift = sum |w_v|
__device__ float d_accp[NSEG][B_ * Qn * Vn];     // chunked partial AV
__device__ float d_sump[NSEG][B_ * Qn];          // chunked partial row sums

__device__ __forceinline__ float tanh_fast(float x) {
    float y;
    asm("tanh.approx.f32 %0, %1;" : "=f"(y) : "f"(x));
    return y;
}

// ---------------------------------------------------------------------------
// Kernel 0: transpose W [H,Din] -> WT [Din,H]  (blocks 0..63)
//           block 64: d_B = sum |w_v|
// ---------------------------------------------------------------------------
__global__ __launch_bounds__(256) void transpose_w(const float* __restrict__ Wq,
                                                   const float* __restrict__ Wk,
                                                   const float* __restrict__ wv) {
    const int blk = blockIdx.x;
    if (blk == 64) {
        if (threadIdx.x < 32) {
            float s = 0.f;
            #pragma unroll
            for (int i = 0; i < 4; i++) s += fabsf(wv[threadIdx.x + 32 * i]);
            #pragma unroll
            for (int off = 16; off; off >>= 1)
                s += __shfl_xor_sync(0xffffffffu, s, off);
            if (threadIdx.x == 0) d_B = s;
        }
        return;
    }
    const int mat = blk >> 5;
    const int t   = blk & 31;
    const int i0 = (t >> 2) * 32;
    const int h0 = (t & 3) * 32;
    const float* __restrict__ W = mat ? Wk : Wq;
    float* __restrict__ WT      = mat ? d_WkT : d_WqT;

    __shared__ float ts[32][33];
    const int tx = threadIdx.x & 31, ty = threadIdx.x >> 5;
    #pragma unroll
    for (int r = 0; r < 4; r++)
        ts[ty + 8 * r][tx] = W[(h0 + ty + 8 * r) * Din + i0 + tx];
    __syncthreads();
    #pragma unroll
    for (int r = 0; r < 4; r++)
        WT[(i0 + ty + 8 * r) * H_ + h0 + tx] = ts[tx][ty + 8 * r];
}

// ---------------------------------------------------------------------------
// Kernel 1: projection GEMM.  BM=16, BN=128, BK=32.  grid=320.
// ---------------------------------------------------------------------------
__global__ __launch_bounds__(256) void proj_gemm(const float* __restrict__ Xq,
                                                 const float* __restrict__ Xk) {
    const int blk = blockIdx.x;
    const float* X; const float* WT; float* out; int row0;
    if (blk < 64) { X = Xq; WT = d_WqT; out = d_qproj; row0 = blk * 16; }
    else          { X = Xk; WT = d_WkT; out = d_kproj; row0 = (blk - 64) * 16; }

    __shared__ float As[32][17];
    __shared__ float Bs[32][128];

    const int tid = threadIdx.x;
    const int tx = tid & 31, ty = tid >> 5;
    float acc[2][4] = {};

    for (int k0 = 0; k0 < Din; k0 += 32) {
        if (tid < 128) {
            const int r = tid >> 3, f = tid & 7;
            float4 v = *(const float4*)&X[(row0 + r) * Din + k0 + f * 4];
            As[f * 4 + 0][r] = v.x; As[f * 4 + 1][r] = v.y;
            As[f * 4 + 2][r] = v.z; As[f * 4 + 3][r] = v.w;
        }
        #pragma unroll
        for (int i = 0; i < 4; i++) {
            const int idx = tid + 256 * i;
            const int kk = idx >> 5, f = idx & 31;
            *(float4*)&Bs[kk][f * 4] = *(const float4*)&WT[(k0 + kk) * H_ + f * 4];
        }
        __syncthreads();

        #pragma unroll
        for (int kk = 0; kk < 32; kk++) {
            const float a0 = As[kk][ty * 2 + 0];
            const float a1 = As[kk][ty * 2 + 1];
            const float4 bv = *(const float4*)&Bs[kk][tx * 4];
            acc[0][0] = fmaf(a0, bv.x, acc[0][0]); acc[0][1] = fmaf(a0, bv.y, acc[0][1]);
            acc[0][2] = fmaf(a0, bv.z, acc[0][2]); acc[0][3] = fmaf(a0, bv.w, acc[0][3]);
            acc[1][0] = fmaf(a1, bv.x, acc[1][0]); acc[1][1] = fmaf(a1, bv.y, acc[1][1]);
            acc[1][2] = fmaf(a1, bv.z, acc[1][2]); acc[1][3] = fmaf(a1, bv.w, acc[1][3]);
        }
        __syncthreads();
    }
    #pragma unroll
    for (int m = 0; m < 2; m++) {
        float4 v = make_float4(acc[m][0], acc[m][1], acc[m][2], acc[m][3]);
        *(float4*)&out[(row0 + ty * 2 + m) * H_ + tx * 4] = v;
    }
}

// ---------------------------------------------------------------------------
// Kernel 2: scores, static strided schedule over live tiles.  grid = 444.
// ---------------------------------------------------------------------------
__global__ __launch_bounds__(256) void score_kernel(const int* __restrict__ valid_lens,
                                                    const float* __restrict__ wv) {
    __shared__ float kt_s[64][132];
    __shared__ float qs[32 * 128];
    __shared__ float wvs[128];

    const int tid = threadIdx.x, lane = tid & 31, w = tid >> 5;

    int vl[4], nkt[4];
    int tot = 0;
    #pragma unroll
    for (int bb = 0; bb < 4; bb++) {
        vl[bb] = valid_lens[bb];
        nkt[bb] = (vl[bb] + 63) >> 6;
        tot += nkt[bb] * 8;
    }
    const float Bsh = d_B;
    if (tid < 128) wvs[tid] = wv[tid];
    __syncthreads();

    for (int wk = blockIdx.x; wk < tot; wk += gridDim.x) {
        int rem = wk, b = 0;
        while (b < 3 && rem >= nkt[b] * 8) { rem -= nkt[b] * 8; b++; }
        const int ktl = rem >> 3, qt = rem & 7;
        const int q0 = qt * 32, k0 = ktl * 64;
        const int valid = vl[b];

        {
            const float4* __restrict__ src = (const float4*)(d_qproj + (b * Qn + q0) * H_);
            #pragma unroll
            for (int i = 0; i < 4; i++)
                ((float4*)qs)[tid + 256 * i] = src[tid + 256 * i];
        }
        #pragma unroll
        for (int i = 0; i < 8; i++) {
            const int idx = tid + 256 * i;
            const int kl = idx >> 5, f = idx & 31;
            *(float4*)&kt_s[kl][f * 4] =
                *(const float4*)&d_kproj[(b * Kn + k0 + kl) * H_ + f * 4];
        }
        __syncthreads();

        const int klh = (w & 1) * 32 + lane;
        const int qb  = (w >> 1) * 8;
        const int kg  = k0 + klh;

        float acc[8] = {};
        #pragma unroll
        for (int h0 = 0; h0 < 128; h0 += 16) {
            const float4 kv0 = *(const float4*)&kt_s[klh][h0 + 0];
            const float4 kv1 = *(const float4*)&kt_s[klh][h0 + 4];
            const float4 kv2 = *(const float4*)&kt_s[klh][h0 + 8];
            const float4 kv3 = *(const float4*)&kt_s[klh][h0 + 12];
            const float4 w0 = *(const float4*)&wvs[h0 + 0];
            const float4 w1 = *(const float4*)&wvs[h0 + 4];
            const float4 w2 = *(const float4*)&wvs[h0 + 8];
            const float4 w3 = *(const float4*)&wvs[h0 + 12];
            #pragma unroll
            for (int qi = 0; qi < 8; qi++) {
                const float* __restrict__ qrow = qs + (qb + qi) * 128 + h0;
                const float4 q0v = *(const float4*)&qrow[0];
                const float4 q1v = *(const float4*)&qrow[4];
                const float4 q2v = *(const float4*)&qrow[8];
                const float4 q3v = *(const float4*)&qrow[12];
                float a = acc[qi];
                a = fmaf(w0.x, tanh_fast(q0v.x + kv0.x), a);
                a = fmaf(w0.y, tanh_fast(q0v.y + kv0.y), a);
                a = fmaf(w0.z, tanh_fast(q0v.z + kv0.z), a);
                a = fmaf(w0.w, tanh_fast(q0v.w + kv0.w), a);
                a = fmaf(w1.x, tanh_fast(q1v.x + kv1.x), a);
                a = fmaf(w1.y, tanh_fast(q1v.y + kv1.y), a);
                a = fmaf(w1.z, tanh_fast(q1v.z + kv1.z), a);
                a = fmaf(w1.w, tanh_fast(q1v.w + kv1.w), a);
                a = fmaf(w2.x, tanh_fast(q2v.x + kv2.x), a);
                a = fmaf(w2.y, tanh_fast(q2v.y + kv2.y), a);
                a = fmaf(w2.z, tanh_fast(q2v.z + kv2.z), a);
                a = fmaf(w2.w, tanh_fast(q2v.w + kv2.w), a);
                a = fmaf(w3.x, tanh_fast(q3v.x + kv3.x), a);
                a = fmaf(w3.y, tanh_fast(q3v.y + kv3.y), a);
                a = fmaf(w3.z, tanh_fast(q3v.z + kv3.z), a);
                a = fmaf(w3.w, tanh_fast(q3v.w + kv3.w), a);
                acc[qi] = a;
            }
        }

        const bool live = (kg < valid);
        #pragma unroll
        for (int qi = 0; qi < 8; qi++) {
            const float p = live ? __expf(acc[qi] - Bsh) : 0.f;
            d_scores[(b * Qn + q0 + qb + qi) * Kn + kg] = p;
        }
        __syncthreads();
    }
}

// ---------------------------------------------------------------------------
// Kernel 3: AV partials v3.  Tile 64q x 64v, BK=64, 256 threads,
// 4q x 4v microtile (16 outputs/thread).  Single smem buffer, no prefetch
// (staging exposure hidden by 3 resident blocks/SM).  Chunk = 2 phases (128k).
// Work item = (b, chunk c, qt, vt).  grid = 592.
// ---------------------------------------------------------------------------
__global__ __launch_bounds__(256, 3) void av_gemm_s(const float* __restrict__ values,
                                                    const int* __restrict__ valid_lens) {
    __shared__ float As[64][68];     // [q][k]
    __shared__ float Bs[64][68];     // [k][v]

    const int tid = threadIdx.x;
    const int tx = tid & 15, ty = tid >> 4;      // tx: v/4 (0..15), ty: q/4 (0..15)

    int nPh[4], cb[4];
    int tot = 0;
    #pragma unroll
    for (int bb = 0; bb < 4; bb++) {
        nPh[bb] = ((valid_lens[bb] + 63) & ~63) >> 6;
        cb[bb]  = (nPh[bb] + 1) >> 1;
        tot += 16 * cb[bb];
    }

    const int sr = tid >> 4, sf = tid & 15;      // staging: row, f4 (16 rows x 16 f4 per 256)

    for (int wk = blockIdx.x; wk < tot; wk += gridDim.x) {
        int rem = wk, b = 0;
        while (b < 3 && rem >= 16 * cb[b]) { rem -= 16 * cb[b]; b++; }
        const int c  = rem >> 4;
        const int sp = rem & 15;
        const int qt = sp >> 2, vt = sp & 3;
        const int q0 = qt * 64, v0 = vt * 64;
        const int phA = 2 * c;
        const int phB = min(nPh[b], 2 * c + 2);

        float4 acc[4];
        float sums[4];
        #pragma unroll
        for (int i = 0; i < 4; i++) { acc[i] = make_float4(0.f, 0.f, 0.f, 0.f); sums[i] = 0.f; }

        for (int ph = phA; ph < phB; ph++) {
            const int k0 = ph * 64;
            // stage As (scores 64q x 64k) and Bs (values 64k x 64v)
            #pragma unroll
            for (int j = 0; j < 4; j++) {
                const int r = sr + 16 * j;
                *(float4*)&As[r][sf * 4] =
                    *(const float4*)&d_scores[(b * Qn + q0 + r) * Kn + k0 + sf * 4];
                *(float4*)&Bs[r][sf * 4] =
                    *(const float4*)&values[((size_t)b * Kn + k0 + r) * Vn + v0 + sf * 4];
            }
            __syncthreads();

            #pragma unroll
            for (int kk4 = 0; kk4 < 16; kk4++) {
                float4 ar[4], bv[4];
                #pragma unroll
                for (int i = 0; i < 4; i++) ar[i] = *(const float4*)&As[4 * ty + i][kk4 * 4];
                #pragma unroll
                for (int j = 0; j < 4; j++) bv[j] = *(const float4*)&Bs[kk4 * 4 + j][tx * 4];
                #pragma unroll
                for (int i = 0; i < 4; i++) {
                    sums[i] += (ar[i].x + ar[i].y) + (ar[i].z + ar[i].w);
                    acc[i].x = fmaf(ar[i].x, bv[0].x, acc[i].x);
                    acc[i].y = fmaf(ar[i].x, bv[0].y, acc[i].y);
                    acc[i].z = fmaf(ar[i].x, bv[0].z, acc[i].z);
                    acc[i].w = fmaf(ar[i].x, bv[0].w, acc[i].w);
                    acc[i].x = fmaf(ar[i].y, bv[1].x, acc[i].x);
                    acc[i].y = fmaf(ar[i].y, bv[1].y, acc[i].y);
                    acc[i].z = fmaf(ar[i].y, bv[1].z, acc[i].z);
                    acc[i].w = fmaf(ar[i].y, bv[1].w, acc[i].w);
                    acc[i].x = fmaf(ar[i].z, bv[2].x, acc[i].x);
                    acc[i].y = fmaf(ar[i].z, bv[2].y, acc[i].y);
                    acc[i].z = fmaf(ar[i].z, bv[2].z, acc[i].z);
                    acc[i].w = fmaf(ar[i].z, bv[2].w, acc[i].w);
                    acc[i].x = fmaf(ar[i].w, bv[3].x, acc[i].x);
                    acc[i].y = fmaf(ar[i].w, bv[3].y, acc[i].y);
                    acc[i].z = fmaf(ar[i].w, bv[3].z, acc[i].z);
                    acc[i].w = fmaf(ar[i].w, bv[3].w, acc[i].w);
                }
            }
            __syncthreads();
        }

        #pragma unroll
        for (int i = 0; i < 4; i++)
            *(float4*)&d_accp[c][(b * Qn + q0 + 4 * ty + i) * Vn + v0 + tx * 4] = acc[i];
        if (vt == 0 && tx == 0) {
            #pragma unroll
            for (int i = 0; i < 4; i++)
                d_sump[c][b * Qn + q0 + 4 * ty + i] = sums[i];
        }
    }
}

// ---------------------------------------------------------------------------
// Kernel 4: combine live chunks + normalize.  grid 256 x 256, float4/thread.
// ---------------------------------------------------------------------------
__global__ __launch_bounds__(256) void combine(const int* __restrict__ valid_lens,
                                               float* __restrict__ out) {
    const int i4 = blockIdx.x * 256 + threadIdx.x;
    const int q  = i4 >> 6;
    const int b  = q >> 8;
    const int nPh = ((valid_lens[b] + 63) & ~63) >> 6;
    const int cbn = (nPh + 1) >> 1;

    float4 a = make_float4(0.f, 0.f, 0.f, 0.f);
    float ssum = 0.f;
    for (int s = 0; s < cbn; s++) {
        const float4 p = ((const float4*)d_accp[s])[i4];
        a.x += p.x; a.y += p.y; a.z += p.z; a.w += p.w;
        ssum += d_sump[s][q];
    }
    const float inv = 1.0f / ssum;
    a.x *= inv; a.y *= inv; a.z *= inv; a.w *= inv;
    ((float4*)out)[i4] = a;
}

extern "C" void kernel_launch(void* const* d_in, const int* in_sizes, int n_in,
                              void* d_out, int out_size) {
    const float* queries    = (const float*)d_in[0];
    const float* keys       = (const float*)d_in[1];
    const float* values     = (const float*)d_in[2];
    const int*   valid_lens = (const int*)  d_in[3];
    const float* W_q        = (const float*)d_in[4];
    const float* W_k        = (const float*)d_in[5];
    const float* w_v        = (const float*)d_in[6];
    float* out              = (float*)d_out;

    transpose_w<<<65, 256>>>(W_q, W_k, w_v);
    proj_gemm<<<320, 256>>>(queries, keys);
    score_kernel<<<444, 256>>>(valid_lens, w_v);
    av_gemm_s<<<592, 256>>>(values, valid_lens);
    combine<<<256, 256>>>(valid_lens, out);
}

// round 15
// speedup vs baseline: 1.1410x; 1.0267x over previous
#include <cuda_runtime.h>

#define B_    4
#define Qn    256
#define Kn    1024
#define Din   256
#define H_    128
#define Vn    256
#define NSEG  16

// Scratch (no cudaMalloc allowed)
__device__ float d_qproj[B_ * Qn * H_];          // [b*Q+q][h]
__device__ float d_kproj[B_ * Kn * H_];          // [b*K+k][h]
__device__ float d_scores[B_ * Qn * Kn];         // p = exp(score - B), zero beyond valid
__device__ float d_WqT[Din * H_];                // [i][h]
__device__ float d_WkT[Din * H_];                // [i][h]
__device__ float d_B;                            // exp shift = sum |w_v|
__device__ float d_accp[NSEG][B_ * Qn * Vn];     // per-phase partial AV
__device__ float d_sump[NSEG][B_ * Qn];          // per-phase partial row sums

__device__ __forceinline__ float tanh_fast(float x) {
    float y;
    asm("tanh.approx.f32 %0, %1;" : "=f"(y) : "f"(x));
    return y;
}

// ---------------------------------------------------------------------------
// Kernel 0: transpose W [H,Din] -> WT [Din,H]  (blocks 0..63)
//           block 64: d_B = sum |w_v|
// ---------------------------------------------------------------------------
__global__ __launch_bounds__(256) void transpose_w(const float* __restrict__ Wq,
                                                   const float* __restrict__ Wk,
                                                   const float* __restrict__ wv) {
    const int blk = blockIdx.x;
    if (blk == 64) {
        if (threadIdx.x < 32) {
            float s = 0.f;
            #pragma unroll
            for (int i = 0; i < 4; i++) s += fabsf(wv[threadIdx.x + 32 * i]);
            #pragma unroll
            for (int off = 16; off; off >>= 1)
                s += __shfl_xor_sync(0xffffffffu, s, off);
            if (threadIdx.x == 0) d_B = s;
        }
        return;
    }
    const int mat = blk >> 5;
    const int t   = blk & 31;
    const int i0 = (t >> 2) * 32;
    const int h0 = (t & 3) * 32;
    const float* __restrict__ W = mat ? Wk : Wq;
    float* __restrict__ WT      = mat ? d_WkT : d_WqT;

    __shared__ float ts[32][33];
    const int tx = threadIdx.x & 31, ty = threadIdx.x >> 5;
    #pragma unroll
    for (int r = 0; r < 4; r++)
        ts[ty + 8 * r][tx] = W[(h0 + ty + 8 * r) * Din + i0 + tx];
    __syncthreads();
    #pragma unroll
    for (int r = 0; r < 4; r++)
        WT[(i0 + ty + 8 * r) * H_ + h0 + tx] = ts[tx][ty + 8 * r];
}

// ---------------------------------------------------------------------------
// Kernel 1: projection GEMM.  BM=16, BN=128, BK=32.  grid=320.
// ---------------------------------------------------------------------------
__global__ __launch_bounds__(256) void proj_gemm(const float* __restrict__ Xq,
                                                 const float* __restrict__ Xk) {
    const int blk = blockIdx.x;
    const float* X; const float* WT; float* out; int row0;
    if (blk < 64) { X = Xq; WT = d_WqT; out = d_qproj; row0 = blk * 16; }
    else          { X = Xk; WT = d_WkT; out = d_kproj; row0 = (blk - 64) * 16; }

    __shared__ float As[32][17];
    __shared__ float Bs[32][128];

    const int tid = threadIdx.x;
    const int tx = tid & 31, ty = tid >> 5;
    float acc[2][4] = {};

    for (int k0 = 0; k0 < Din; k0 += 32) {
        if (tid < 128) {
            const int r = tid >> 3, f = tid & 7;
            float4 v = *(const float4*)&X[(row0 + r) * Din + k0 + f * 4];
            As[f * 4 + 0][r] = v.x; As[f * 4 + 1][r] = v.y;
            As[f * 4 + 2][r] = v.z; As[f * 4 + 3][r] = v.w;
        }
        #pragma unroll
        for (int i = 0; i < 4; i++) {
            const int idx = tid + 256 * i;
            const int kk = idx >> 5, f = idx & 31;
            *(float4*)&Bs[kk][f * 4] = *(const float4*)&WT[(k0 + kk) * H_ + f * 4];
        }
        __syncthreads();

        #pragma unroll
        for (int kk = 0; kk < 32; kk++) {
            const float a0 = As[kk][ty * 2 + 0];
            const float a1 = As[kk][ty * 2 + 1];
            const float4 bv = *(const float4*)&Bs[kk][tx * 4];
            acc[0][0] = fmaf(a0, bv.x, acc[0][0]); acc[0][1] = fmaf(a0, bv.y, acc[0][1]);
            acc[0][2] = fmaf(a0, bv.z, acc[0][2]); acc[0][3] = fmaf(a0, bv.w, acc[0][3]);
            acc[1][0] = fmaf(a1, bv.x, acc[1][0]); acc[1][1] = fmaf(a1, bv.y, acc[1][1]);
            acc[1][2] = fmaf(a1, bv.z, acc[1][2]); acc[1][3] = fmaf(a1, bv.w, acc[1][3]);
        }
        __syncthreads();
    }
    #pragma unroll
    for (int m = 0; m < 2; m++) {
        float4 v = make_float4(acc[m][0], acc[m][1], acc[m][2], acc[m][3]);
        *(float4*)&out[(row0 + ty * 2 + m) * H_ + tx * 4] = v;
    }
}

// ---------------------------------------------------------------------------
// Kernel 2: scores, static strided schedule over live tiles.  grid = 444.
// ---------------------------------------------------------------------------
__global__ __launch_bounds__(256) void score_kernel(const int* __restrict__ valid_lens,
                                                    const float* __restrict__ wv) {
    __shared__ float kt_s[64][132];
    __shared__ float qs[32 * 128];
    __shared__ float wvs[128];

    const int tid = threadIdx.x, lane = tid & 31, w = tid >> 5;

    int vl[4], nkt[4];
    int tot = 0;
    #pragma unroll
    for (int bb = 0; bb < 4; bb++) {
        vl[bb] = valid_lens[bb];
        nkt[bb] = (vl[bb] + 63) >> 6;
        tot += nkt[bb] * 8;
    }
    const float Bsh = d_B;
    if (tid < 128) wvs[tid] = wv[tid];
    __syncthreads();

    for (int wk = blockIdx.x; wk < tot; wk += gridDim.x) {
        int rem = wk, b = 0;
        while (b < 3 && rem >= nkt[b] * 8) { rem -= nkt[b] * 8; b++; }
        const int ktl = rem >> 3, qt = rem & 7;
        const int q0 = qt * 32, k0 = ktl * 64;
        const int valid = vl[b];

        {
            const float4* __restrict__ src = (const float4*)(d_qproj + (b * Qn + q0) * H_);
            #pragma unroll
            for (int i = 0; i < 4; i++)
                ((float4*)qs)[tid + 256 * i] = src[tid + 256 * i];
        }
        #pragma unroll
        for (int i = 0; i < 8; i++) {
            const int idx = tid + 256 * i;
            const int kl = idx >> 5, f = idx & 31;
            *(float4*)&kt_s[kl][f * 4] =
                *(const float4*)&d_kproj[(b * Kn + k0 + kl) * H_ + f * 4];
        }
        __syncthreads();

        const int klh = (w & 1) * 32 + lane;
        const int qb  = (w >> 1) * 8;
        const int kg  = k0 + klh;

        float acc[8] = {};
        #pragma unroll
        for (int h0 = 0; h0 < 128; h0 += 16) {
            const float4 kv0 = *(const float4*)&kt_s[klh][h0 + 0];
            const float4 kv1 = *(const float4*)&kt_s[klh][h0 + 4];
            const float4 kv2 = *(const float4*)&kt_s[klh][h0 + 8];
            const float4 kv3 = *(const float4*)&kt_s[klh][h0 + 12];
            const float4 w0 = *(const float4*)&wvs[h0 + 0];
            const float4 w1 = *(const float4*)&wvs[h0 + 4];
            const float4 w2 = *(const float4*)&wvs[h0 + 8];
            const float4 w3 = *(const float4*)&wvs[h0 + 12];
            #pragma unroll
            for (int qi = 0; qi < 8; qi++) {
                const float* __restrict__ qrow = qs + (qb + qi) * 128 + h0;
                const float4 q0v = *(const float4*)&qrow[0];
                const float4 q1v = *(const float4*)&qrow[4];
                const float4 q2v = *(const float4*)&qrow[8];
                const float4 q3v = *(const float4*)&qrow[12];
                float a = acc[qi];
                a = fmaf(w0.x, tanh_fast(q0v.x + kv0.x), a);
                a = fmaf(w0.y, tanh_fast(q0v.y + kv0.y), a);
                a = fmaf(w0.z, tanh_fast(q0v.z + kv0.z), a);
                a = fmaf(w0.w, tanh_fast(q0v.w + kv0.w), a);
                a = fmaf(w1.x, tanh_fast(q1v.x + kv1.x), a);
                a = fmaf(w1.y, tanh_fast(q1v.y + kv1.y), a);
                a = fmaf(w1.z, tanh_fast(q1v.z + kv1.z), a);
                a = fmaf(w1.w, tanh_fast(q1v.w + kv1.w), a);
                a = fmaf(w2.x, tanh_fast(q2v.x + kv2.x), a);
                a = fmaf(w2.y, tanh_fast(q2v.y + kv2.y), a);
                a = fmaf(w2.z, tanh_fast(q2v.z + kv2.z), a);
                a = fmaf(w2.w, tanh_fast(q2v.w + kv2.w), a);
                a = fmaf(w3.x, tanh_fast(q3v.x + kv3.x), a);
                a = fmaf(w3.y, tanh_fast(q3v.y + kv3.y), a);
                a = fmaf(w3.z, tanh_fast(q3v.z + kv3.z), a);
                a = fmaf(w3.w, tanh_fast(q3v.w + kv3.w), a);
                acc[qi] = a;
            }
        }

        const bool live = (kg < valid);
        #pragma unroll
        for (int qi = 0; qi < 8; qi++) {
            const float p = live ? __expf(acc[qi] - Bsh) : 0.f;
            d_scores[(b * Qn + q0 + qb + qi) * Kn + kg] = p;
        }
        __syncthreads();
    }
}

// ---------------------------------------------------------------------------
// Kernel 3: AV partials.  Tile 64q x 64v, BK=64, 256 threads, 4q x 4v
// microtile.  Work item = (b, phase c, qt, vt): ONE 64k phase per item.
// grid = 296 (exactly 2 resident blocks/SM; partner block hides staging).
// Partials to slot c (deterministic).
// ---------------------------------------------------------------------------
__global__ __launch_bounds__(256, 3) void av_gemm_s(const float* __restrict__ values,
                                                    const int* __restrict__ valid_lens) {
    __shared__ float As[64][68];     // [q][k]
    __shared__ float Bs[64][68];     // [k][v]

    const int tid = threadIdx.x;
    const int tx = tid & 15, ty = tid >> 4;      // tx: v/4 (0..15), ty: q/4 (0..15)

    int nPh[4];
    int tot = 0;
    #pragma unroll
    for (int bb = 0; bb < 4; bb++) {
        nPh[bb] = ((valid_lens[bb] + 63) & ~63) >> 6;
        tot += 16 * nPh[bb];
    }

    const int sr = tid >> 4, sf = tid & 15;      // staging: row, f4

    for (int wk = blockIdx.x; wk < tot; wk += gridDim.x) {
        int rem = wk, b = 0;
        while (b < 3 && rem >= 16 * nPh[b]) { rem -= 16 * nPh[b]; b++; }
        const int c  = rem >> 4;                 // phase index = partial slot
        const int sp = rem & 15;
        const int qt = sp >> 2, vt = sp & 3;
        const int q0 = qt * 64, v0 = vt * 64;
        const int k0 = c * 64;

        float4 acc[4];
        float sums[4];
        #pragma unroll
        for (int i = 0; i < 4; i++) { acc[i] = make_float4(0.f, 0.f, 0.f, 0.f); sums[i] = 0.f; }

        // stage As (scores 64q x 64k) and Bs (values 64k x 64v)
        #pragma unroll
        for (int j = 0; j < 4; j++) {
            const int r = sr + 16 * j;
            *(float4*)&As[r][sf * 4] =
                *(const float4*)&d_scores[(b * Qn + q0 + r) * Kn + k0 + sf * 4];
            *(float4*)&Bs[r][sf * 4] =
                *(const float4*)&values[((size_t)b * Kn + k0 + r) * Vn + v0 + sf * 4];
        }
        __syncthreads();

        #pragma unroll
        for (int kk4 = 0; kk4 < 16; kk4++) {
            float4 ar[4], bv[4];
            #pragma unroll
            for (int i = 0; i < 4; i++) ar[i] = *(const float4*)&As[4 * ty + i][kk4 * 4];
            #pragma unroll
            for (int j = 0; j < 4; j++) bv[j] = *(const float4*)&Bs[kk4 * 4 + j][tx * 4];
            #pragma unroll
            for (int i = 0; i < 4; i++) {
                sums[i] += (ar[i].x + ar[i].y) + (ar[i].z + ar[i].w);
                acc[i].x = fmaf(ar[i].x, bv[0].x, acc[i].x);
                acc[i].y = fmaf(ar[i].x, bv[0].y, acc[i].y);
                acc[i].z = fmaf(ar[i].x, bv[0].z, acc[i].z);
                acc[i].w = fmaf(ar[i].x, bv[0].w, acc[i].w);
                acc[i].x = fmaf(ar[i].y, bv[1].x, acc[i].x);
                acc[i].y = fmaf(ar[i].y, bv[1].y, acc[i].y);
                acc[i].z = fmaf(ar[i].y, bv[1].z, acc[i].z);
                acc[i].w = fmaf(ar[i].y, bv[1].w, acc[i].w);
                acc[i].x = fmaf(ar[i].z, bv[2].x, acc[i].x);
                acc[i].y = fmaf(ar[i].z, bv[2].y, acc[i].y);
                acc[i].z = fmaf(ar[i].z, bv[2].z, acc[i].z);
                acc[i].w = fmaf(ar[i].z, bv[2].w, acc[i].w);
                acc[i].x = fmaf(ar[i].w, bv[3].x, acc[i].x);
                acc[i].y = fmaf(ar[i].w, bv[3].y, acc[i].y);
                acc[i].z = fmaf(ar[i].w, bv[3].z, acc[i].z);
                acc[i].w = fmaf(ar[i].w, bv[3].w, acc[i].w);
            }
        }
        __syncthreads();

        #pragma unroll
        for (int i = 0; i < 4; i++)
            *(float4*)&d_accp[c][(b * Qn + q0 + 4 * ty + i) * Vn + v0 + tx * 4] = acc[i];
        if (vt == 0 && tx == 0) {
            #pragma unroll
            for (int i = 0; i < 4; i++)
                d_sump[c][b * Qn + q0 + 4 * ty + i] = sums[i];
        }
    }
}

// ---------------------------------------------------------------------------
// Kernel 4: combine live phase-partials + normalize.  grid 256 x 256.
// Only reads slots s < nPh_b (stale slots never touched).
// ---------------------------------------------------------------------------
__global__ __launch_bounds__(256) void combine(const int* __restrict__ valid_lens,
                                               float* __restrict__ out) {
    const int i4 = blockIdx.x * 256 + threadIdx.x;
    const int q  = i4 >> 6;
    const int b  = q >> 8;
    const int cbn = ((valid_lens[b] + 63) & ~63) >> 6;   // = nPh_b

    float4 a = make_float4(0.f, 0.f, 0.f, 0.f);
    float ssum = 0.f;
    for (int s = 0; s < cbn; s++) {
        const float4 p = ((const float4*)d_accp[s])[i4];
        a.x += p.x; a.y += p.y; a.z += p.z; a.w += p.w;
        ssum += d_sump[s][q];
    }
    const float inv = 1.0f / ssum;
    a.x *= inv; a.y *= inv; a.z *= inv; a.w *= inv;
    ((float4*)out)[i4] = a;
}

extern "C" void kernel_launch(void* const* d_in, const int* in_sizes, int n_in,
                              void* d_out, int out_size) {
    const float* queries    = (const float*)d_in[0];
    const float* keys       = (const float*)d_in[1];
    const float* values     = (const float*)d_in[2];
    const int*   valid_lens = (const int*)  d_in[3];
    const float* W_q        = (const float*)d_in[4];
    const float* W_k        = (const float*)d_in[5];
    const float* w_v        = (const float*)d_in[6];
    float* out              = (float*)d_out;

    transpose_w<<<65, 256>>>(W_q, W_k, w_v);
    proj_gemm<<<320, 256>>>(queries, keys);
    score_kernel<<<444, 256>>>(valid_lens, w_v);
    av_gemm_s<<<296, 256>>>(values, valid_lens);
    combine<<<256, 256>>>(valid_lens, out);
}